// round 5
// baseline (speedup 1.0000x reference)
#include <cuda_runtime.h>

#define NN 50000
#define NE 800000
#define D  256
#define DOUT 128

// ---------------- scratch (static device memory; allocation-free) ----------------
__device__ float g_h  [NN * D];
__device__ float g_h2 [NN * D];
__device__ float g_agg[NN * D];
__device__ int   g_deg[NN];
__device__ int   g_off[NN + 1];
__device__ int   g_cur[NN];
__device__ int   g_src[NE];
__device__ int   g_esrc[NE];
__device__ int   g_edst[NE];
__device__ int   g_flag[1];

// ---------------- edge dtype probe + conversion ----------------
// If edge_index is int64, values are node ids < NN. If it is actually int32
// (read here as int64), values fuse two ids -> ~2^32 scale. Decide per launch.
__global__ void probe_kernel(const void* __restrict__ ei, int* __restrict__ flag) {
    if (threadIdx.x == 0 && blockIdx.x == 0) {
        const long long* p = (const long long*)ei;
        int f = 0;
        for (int i = 0; i < 64; i++) {
            long long v = p[i];
            if (v < 0 || v >= NN) { f = 1; break; }
        }
        flag[0] = f;   // 1 => int32 layout, 0 => int64 layout
    }
}

__global__ void convert_edges_kernel(const void* __restrict__ ei,
                                     const int* __restrict__ flag,
                                     int* __restrict__ es, int* __restrict__ ed) {
    int e = blockIdx.x * blockDim.x + threadIdx.x;
    if (e >= NE) return;
    int s, d;
    if (flag[0]) {
        const int* p = (const int*)ei;
        s = p[e]; d = p[NE + e];
    } else {
        const long long* p = (const long long*)ei;
        s = (int)p[e]; d = (int)p[NE + e];
    }
    if ((unsigned)s >= NN) s = 0;   // defensive: never feed atomics a wild index
    if ((unsigned)d >= NN) d = 0;
    es[e] = s;
    ed[e] = d;
}

// ---------------- CSR build ----------------
__global__ void zero_deg_kernel(int* __restrict__ deg) {
    int i = blockIdx.x * blockDim.x + threadIdx.x;
    if (i < NN) deg[i] = 0;
}

__global__ void deg_count_kernel(const int* __restrict__ ed, int* __restrict__ deg) {
    int e = blockIdx.x * blockDim.x + threadIdx.x;
    if (e < NE) atomicAdd(&deg[ed[e]], 1);
}

// single-block scan over NN degrees -> exclusive offsets (+cursor copy)
__global__ void scan_kernel(const int* __restrict__ deg, int* __restrict__ off,
                            int* __restrict__ cur) {
    __shared__ int s[1024];
    int t = threadIdx.x;
    const int chunk = (NN + 1023) / 1024;   // 49
    int base = t * chunk;
    int sum = 0;
    for (int i = 0; i < chunk; i++) {
        int idx = base + i;
        if (idx < NN) sum += deg[idx];
    }
    s[t] = sum;
    __syncthreads();
    for (int o = 1; o < 1024; o <<= 1) {
        int v = (t >= o) ? s[t - o] : 0;
        __syncthreads();
        s[t] += v;
        __syncthreads();
    }
    int run = (t == 0) ? 0 : s[t - 1];
    for (int i = 0; i < chunk; i++) {
        int idx = base + i;
        if (idx < NN) {
            off[idx] = run;
            cur[idx] = run;
            run += deg[idx];
        }
    }
    if (t == 1023) off[NN] = s[1023];
}

__global__ void csr_fill_kernel(const int* __restrict__ es, const int* __restrict__ ed,
                                int* __restrict__ cur, int* __restrict__ srcarr) {
    int e = blockIdx.x * blockDim.x + threadIdx.x;
    if (e >= NE) return;
    int p = atomicAdd(&cur[ed[e]], 1);
    if ((unsigned)p < NE) srcarr[p] = es[e];
}

// ---------------- mean aggregation: block per node, thread per column ----------------
__global__ __launch_bounds__(256) void agg_kernel(const float* __restrict__ in,
                                                  const int* __restrict__ off,
                                                  const int* __restrict__ srcarr,
                                                  float* __restrict__ aggout) {
    int node = blockIdx.x;
    int c = threadIdx.x;
    int b = off[node];
    int e = off[node + 1];
    int deg = e - b;
    float acc = 0.f;
    int i = b;
    for (; i + 4 <= e; i += 4) {
        int s0 = srcarr[i], s1 = srcarr[i + 1], s2 = srcarr[i + 2], s3 = srcarr[i + 3];
        float v0 = in[s0 * D + c];
        float v1 = in[s1 * D + c];
        float v2 = in[s2 * D + c];
        float v3 = in[s3 * D + c];
        acc += v0; acc += v1; acc += v2; acc += v3;
    }
    for (; i < e; ++i) acc += in[srcarr[i] * D + c];
    aggout[node * D + c] = acc / fmaxf((float)deg, 1.0f);
}

// ---------------- tiled SGEMM: C = act(A1@W1 + bias [+ A2@W2]) ----------------
__global__ __launch_bounds__(256) void gemm64_kernel(
    const float* __restrict__ A1, const float* __restrict__ W1,
    const float* __restrict__ bias,
    const float* __restrict__ A2, const float* __restrict__ W2,
    float* __restrict__ C, int M, int N, int relu)
{
    __shared__ float As[16][68];
    __shared__ float Bs[16][64];

    int bm0 = blockIdx.x * 64;
    int bn0 = blockIdx.y * 64;
    int t = threadIdx.x;
    int ar = t >> 2, ac = (t & 3) * 4;
    int br = t >> 4, bc = (t & 15) * 4;
    int tx = t & 15, ty = t >> 4;

    float acc[4][4];
#pragma unroll
    for (int i = 0; i < 4; i++)
#pragma unroll
        for (int j = 0; j < 4; j++) acc[i][j] = 0.f;

    int nkt = (A2 != nullptr) ? 32 : 16;
    for (int kt = 0; kt < nkt; kt++) {
        const float* A = (kt < 16) ? A1 : A2;
        const float* W = (kt < 16) ? W1 : W2;
        int k0 = (kt & 15) * 16;

        int grow = bm0 + ar;
        float4 av = make_float4(0.f, 0.f, 0.f, 0.f);
        if (grow < M) av = *(const float4*)&A[grow * D + k0 + ac];
        As[ac + 0][ar] = av.x;
        As[ac + 1][ar] = av.y;
        As[ac + 2][ar] = av.z;
        As[ac + 3][ar] = av.w;

        *(float4*)&Bs[br][bc] = *(const float4*)&W[(k0 + br) * N + bn0 + bc];
        __syncthreads();

#pragma unroll
        for (int k = 0; k < 16; k++) {
            float4 a = *(const float4*)&As[k][ty * 4];
            float4 b = *(const float4*)&Bs[k][tx * 4];
            acc[0][0] += a.x * b.x; acc[0][1] += a.x * b.y; acc[0][2] += a.x * b.z; acc[0][3] += a.x * b.w;
            acc[1][0] += a.y * b.x; acc[1][1] += a.y * b.y; acc[1][2] += a.y * b.z; acc[1][3] += a.y * b.w;
            acc[2][0] += a.z * b.x; acc[2][1] += a.z * b.y; acc[2][2] += a.z * b.z; acc[2][3] += a.z * b.w;
            acc[3][0] += a.w * b.x; acc[3][1] += a.w * b.y; acc[3][2] += a.w * b.z; acc[3][3] += a.w * b.w;
        }
        __syncthreads();
    }

    float bj[4];
#pragma unroll
    for (int j = 0; j < 4; j++) bj[j] = bias[bn0 + tx * 4 + j];

#pragma unroll
    for (int i = 0; i < 4; i++) {
        int gm = bm0 + ty * 4 + i;
        if (gm >= M) continue;
#pragma unroll
        for (int j = 0; j < 4; j++) {
            int gn = bn0 + tx * 4 + j;
            float v = acc[i][j] + bj[j];
            if (relu) v = fmaxf(v, 0.f);
            C[gm * N + gn] = v;
        }
    }
}

// ---------------- mp2 (256x128) + log_softmax, block per node ----------------
__global__ __launch_bounds__(128) void mp2_lsm_kernel(
    const float* __restrict__ h,
    const float* __restrict__ w2, const float* __restrict__ b2,
    float* __restrict__ out)
{
    __shared__ float sh[256];
    __shared__ float red[128];
    int node = blockIdx.x;
    int t = threadIdx.x;
    sh[t]       = h[node * D + t];
    sh[t + 128] = h[node * D + t + 128];
    __syncthreads();

    float acc = b2[t];
#pragma unroll 8
    for (int k = 0; k < 256; k++)
        acc += sh[k] * w2[k * DOUT + t];

    red[t] = acc;
    __syncthreads();
    for (int s = 64; s > 0; s >>= 1) {
        if (t < s) red[t] = fmaxf(red[t], red[t + s]);
        __syncthreads();
    }
    float mx = red[0];
    __syncthreads();
    red[t] = expf(acc - mx);
    __syncthreads();
    for (int s = 64; s > 0; s >>= 1) {
        if (t < s) red[t] += red[t + s];
        __syncthreads();
    }
    float lse = mx + logf(red[0]);
    out[node * DOUT + t] = acc - lse;
}

// ---------------- launch ----------------
extern "C" void kernel_launch(void* const* d_in, const int* in_sizes, int n_in,
                              void* d_out, int out_size)
{
    const float* x  = (const float*)d_in[0];
    const void*  ei = d_in[1];                    // int32 OR int64 — probed at runtime
    const float* wl = (const float*)d_in[2];
    const float* bl = (const float*)d_in[3];
    const float* wr = (const float*)d_in[4];
    const float* w1 = (const float*)d_in[5];
    const float* b1 = (const float*)d_in[6];
    const float* w2 = (const float*)d_in[7];
    const float* b2 = (const float*)d_in[8];
    float* out = (float*)d_out;

    float *h, *h2, *agg;
    int *deg, *off, *cur, *srcp, *esrc, *edst, *flag;
    cudaGetSymbolAddress((void**)&h,    g_h);
    cudaGetSymbolAddress((void**)&h2,   g_h2);
    cudaGetSymbolAddress((void**)&agg,  g_agg);
    cudaGetSymbolAddress((void**)&deg,  g_deg);
    cudaGetSymbolAddress((void**)&off,  g_off);
    cudaGetSymbolAddress((void**)&cur,  g_cur);
    cudaGetSymbolAddress((void**)&srcp, g_src);
    cudaGetSymbolAddress((void**)&esrc, g_esrc);
    cudaGetSymbolAddress((void**)&edst, g_edst);
    cudaGetSymbolAddress((void**)&flag, g_flag);

    // Edge dtype probe + normalization to int32 src/dst
    probe_kernel        <<<1, 32>>>(ei, flag);
    convert_edges_kernel<<<(NE + 255) / 256, 256>>>(ei, flag, esrc, edst);

    // CSR build (once per launch; edges fixed across layers)
    zero_deg_kernel <<<(NN + 255) / 256, 256>>>(deg);
    deg_count_kernel<<<(NE + 255) / 256, 256>>>(edst, deg);
    scan_kernel     <<<1, 1024>>>(deg, off, cur);
    csr_fill_kernel <<<(NE + 255) / 256, 256>>>(esrc, edst, cur, srcp);

    dim3 gg((NN + 63) / 64, D / 64);   // (782, 4)

    // layer 0: in = x
    agg_kernel <<<NN, 256>>>(x, off, srcp, agg);
    gemm64_kernel<<<gg, 256>>>(agg, wl + 0 * D * D, bl + 0 * D, x,  wr + 0 * D * D, h,  NN, D, 1);
    // layer 1: in = h
    agg_kernel <<<NN, 256>>>(h, off, srcp, agg);
    gemm64_kernel<<<gg, 256>>>(agg, wl + 1 * D * D, bl + 1 * D, h,  wr + 1 * D * D, h2, NN, D, 1);
    // layer 2: in = h2
    agg_kernel <<<NN, 256>>>(h2, off, srcp, agg);
    gemm64_kernel<<<gg, 256>>>(agg, wl + 2 * D * D, bl + 2 * D, h2, wr + 2 * D * D, h,  NN, D, 1);

    // post_mp linear 1 (no activation)
    gemm64_kernel<<<gg, 256>>>(h, w1, b1, nullptr, nullptr, h2, NN, D, 0);

    // post_mp linear 2 + log_softmax
    mp2_lsm_kernel<<<NN, 128>>>(h2, w2, b2, out);
}

// round 9
// speedup vs baseline: 1.7984x; 1.7984x over previous
#include <cuda_runtime.h>

#define NN 50000
#define NE 800000
#define D  256
#define DOUT 128

// ---------------- scratch (static device memory; allocation-free) ----------------
__device__ float g_h  [NN * D];
__device__ float g_h2 [NN * D];
__device__ float g_agg[NN * D];
__device__ float g_w12[D * DOUT];
__device__ float g_b12[DOUT];
__device__ int   g_deg[NN];
__device__ int   g_off[NN + 1];
__device__ int   g_cur[NN];
__device__ int   g_src[NE];
__device__ int   g_esrc[NE];
__device__ int   g_edst[NE];
__device__ int   g_flag[1];

// ---------------- edge dtype probe + conversion ----------------
__global__ void probe_kernel(const void* __restrict__ ei, int* __restrict__ flag) {
    if (threadIdx.x == 0 && blockIdx.x == 0) {
        const long long* p = (const long long*)ei;
        int f = 0;
        for (int i = 0; i < 64; i++) {
            long long v = p[i];
            if (v < 0 || v >= NN) { f = 1; break; }
        }
        flag[0] = f;   // 1 => int32 layout, 0 => int64 layout
    }
}

__global__ void convert_edges_kernel(const void* __restrict__ ei,
                                     const int* __restrict__ flag,
                                     int* __restrict__ es, int* __restrict__ ed) {
    int e = blockIdx.x * blockDim.x + threadIdx.x;
    if (e >= NE) return;
    int s, d;
    if (flag[0]) {
        const int* p = (const int*)ei;
        s = p[e]; d = p[NE + e];
    } else {
        const long long* p = (const long long*)ei;
        s = (int)p[e]; d = (int)p[NE + e];
    }
    if ((unsigned)s >= NN) s = 0;
    if ((unsigned)d >= NN) d = 0;
    es[e] = s;
    ed[e] = d;
}

// ---------------- CSR build ----------------
__global__ void zero_deg_kernel(int* __restrict__ deg) {
    int i = blockIdx.x * blockDim.x + threadIdx.x;
    if (i < NN) deg[i] = 0;
}

__global__ void deg_count_kernel(const int* __restrict__ ed, int* __restrict__ deg) {
    int e = blockIdx.x * blockDim.x + threadIdx.x;
    if (e < NE) atomicAdd(&deg[ed[e]], 1);
}

__global__ void scan_kernel(const int* __restrict__ deg, int* __restrict__ off,
                            int* __restrict__ cur) {
    __shared__ int s[1024];
    int t = threadIdx.x;
    const int chunk = (NN + 1023) / 1024;   // 49
    int base = t * chunk;
    int sum = 0;
    for (int i = 0; i < chunk; i++) {
        int idx = base + i;
        if (idx < NN) sum += deg[idx];
    }
    s[t] = sum;
    __syncthreads();
    for (int o = 1; o < 1024; o <<= 1) {
        int v = (t >= o) ? s[t - o] : 0;
        __syncthreads();
        s[t] += v;
        __syncthreads();
    }
    int run = (t == 0) ? 0 : s[t - 1];
    for (int i = 0; i < chunk; i++) {
        int idx = base + i;
        if (idx < NN) {
            off[idx] = run;
            cur[idx] = run;
            run += deg[idx];
        }
    }
    if (t == 1023) off[NN] = s[1023];
}

__global__ void csr_fill_kernel(const int* __restrict__ es, const int* __restrict__ ed,
                                int* __restrict__ cur, int* __restrict__ srcarr) {
    int e = blockIdx.x * blockDim.x + threadIdx.x;
    if (e >= NE) return;
    int p = atomicAdd(&cur[ed[e]], 1);
    if ((unsigned)p < NE) srcarr[p] = es[e];
}

// ---------------- fold post_mp: w12 = w1@w2, b12 = b1@w2 + b2 ----------------
__global__ __launch_bounds__(128) void w12_kernel(
    const float* __restrict__ w1, const float* __restrict__ b1,
    const float* __restrict__ w2, const float* __restrict__ b2,
    float* __restrict__ w12, float* __restrict__ b12)
{
    __shared__ float row[256];
    int i = blockIdx.x;     // 0..255 (w1 row)
    int t = threadIdx.x;    // 0..127 (output col)
    row[t]       = w1[i * D + t];
    row[t + 128] = w1[i * D + t + 128];
    __syncthreads();
    float acc = 0.f;
#pragma unroll 8
    for (int k = 0; k < D; k++)
        acc += row[k] * w2[k * DOUT + t];
    w12[i * DOUT + t] = acc;
    if (i == 0) {
        float bacc = b2[t];
        for (int k = 0; k < D; k++)
            bacc += b1[k] * w2[k * DOUT + t];
        b12[t] = bacc;
    }
}

// ---------------- mean aggregation: block per node, thread per column ----------------
__global__ __launch_bounds__(256) void agg_kernel(const float* __restrict__ in,
                                                  const int* __restrict__ off,
                                                  const int* __restrict__ srcarr,
                                                  float* __restrict__ aggout) {
    int node = blockIdx.x;
    int c = threadIdx.x;
    int b = off[node];
    int e = off[node + 1];
    int deg = e - b;
    float acc = 0.f;
    int i = b;
    for (; i + 4 <= e; i += 4) {
        int s0 = srcarr[i], s1 = srcarr[i + 1], s2 = srcarr[i + 2], s3 = srcarr[i + 3];
        float v0 = in[s0 * D + c];
        float v1 = in[s1 * D + c];
        float v2 = in[s2 * D + c];
        float v3 = in[s3 * D + c];
        acc += v0; acc += v1; acc += v2; acc += v3;
    }
    for (; i < e; ++i) acc += in[srcarr[i] * D + c];
    aggout[node * D + c] = acc / fmaxf((float)deg, 1.0f);
}

// ---------------- dual SGEMM: C = relu(A1@W1 + bias + A2@W2) ----------------
// Tile 128x64, BK=16, 256 threads, 8x4/thread, double-buffered smem.
__global__ __launch_bounds__(256) void gemm128_kernel(
    const float* __restrict__ A1, const float* __restrict__ W1,
    const float* __restrict__ bias,
    const float* __restrict__ A2, const float* __restrict__ W2,
    float* __restrict__ C, int M)
{
    __shared__ float As[2][16][132];   // [buf][k][m], stride 132 keeps 16B alignment
    __shared__ float Bs[2][16][64];

    int t = threadIdx.x;
    int bm0 = blockIdx.x * 128;
    int bn0 = blockIdx.y * 64;

    int ar = t >> 1;            // 0..127 : A row within tile
    int ac = (t & 1) * 8;       // 0 or 8 : A col group
    int br = t >> 4;            // 0..15  : B row
    int bc = (t & 15) * 4;      // B col group
    int ty = t >> 4;            // 0..15  : output row group (8 rows)
    int tx = t & 15;            // output col group (4 cols)

    int grow = bm0 + ar;
    bool arow_ok = (grow < M);
    const int nkt = 32;

    float acc[8][4];
#pragma unroll
    for (int i = 0; i < 8; i++)
#pragma unroll
        for (int j = 0; j < 4; j++) acc[i][j] = 0.f;

    // prologue: tile 0 -> buffer 0
    {
        float4 av0 = make_float4(0.f, 0.f, 0.f, 0.f);
        float4 av1 = make_float4(0.f, 0.f, 0.f, 0.f);
        if (arow_ok) {
            const float* ap = &A1[grow * D + ac];
            av0 = *(const float4*)ap;
            av1 = *(const float4*)(ap + 4);
        }
        float4 bv = *(const float4*)&W1[br * D + bn0 + bc];
        As[0][ac + 0][ar] = av0.x;
        As[0][ac + 1][ar] = av0.y;
        As[0][ac + 2][ar] = av0.z;
        As[0][ac + 3][ar] = av0.w;
        As[0][ac + 4][ar] = av1.x;
        As[0][ac + 5][ar] = av1.y;
        As[0][ac + 6][ar] = av1.z;
        As[0][ac + 7][ar] = av1.w;
        *(float4*)&Bs[0][br][bc] = bv;
    }
    __syncthreads();

    for (int kt = 0; kt < nkt; kt++) {
        int buf = kt & 1;
        bool have_next = (kt + 1 < nkt);
        float4 av0n = make_float4(0.f, 0.f, 0.f, 0.f);
        float4 av1n = make_float4(0.f, 0.f, 0.f, 0.f);
        float4 bvn;
        if (have_next) {
            int ktn = kt + 1;
            const float* A = (ktn < 16) ? A1 : A2;
            const float* W = (ktn < 16) ? W1 : W2;
            int k0 = (ktn & 15) * 16;
            if (arow_ok) {
                const float* ap = &A[grow * D + k0 + ac];
                av0n = *(const float4*)ap;
                av1n = *(const float4*)(ap + 4);
            }
            bvn = *(const float4*)&W[(k0 + br) * D + bn0 + bc];
        }

#pragma unroll
        for (int k = 0; k < 16; k++) {
            float4 a0 = *(const float4*)&As[buf][k][ty * 8];
            float4 a1 = *(const float4*)&As[buf][k][ty * 8 + 4];
            float4 b  = *(const float4*)&Bs[buf][k][tx * 4];
            float am[8] = {a0.x, a0.y, a0.z, a0.w, a1.x, a1.y, a1.z, a1.w};
#pragma unroll
            for (int i = 0; i < 8; i++) {
                acc[i][0] += am[i] * b.x;
                acc[i][1] += am[i] * b.y;
                acc[i][2] += am[i] * b.z;
                acc[i][3] += am[i] * b.w;
            }
        }

        if (have_next) {
            int nb = buf ^ 1;
            As[nb][ac + 0][ar] = av0n.x;
            As[nb][ac + 1][ar] = av0n.y;
            As[nb][ac + 2][ar] = av0n.z;
            As[nb][ac + 3][ar] = av0n.w;
            As[nb][ac + 4][ar] = av1n.x;
            As[nb][ac + 5][ar] = av1n.y;
            As[nb][ac + 6][ar] = av1n.z;
            As[nb][ac + 7][ar] = av1n.w;
            *(float4*)&Bs[nb][br][bc] = bvn;
            __syncthreads();
        }
    }

    float4 bj = *(const float4*)&bias[bn0 + tx * 4];
#pragma unroll
    for (int i = 0; i < 8; i++) {
        int gm = bm0 + ty * 8 + i;
        if (gm >= M) continue;
        float4 o;
        o.x = fmaxf(acc[i][0] + bj.x, 0.f);
        o.y = fmaxf(acc[i][1] + bj.y, 0.f);
        o.z = fmaxf(acc[i][2] + bj.z, 0.f);
        o.w = fmaxf(acc[i][3] + bj.w, 0.f);
        *(float4*)&C[gm * D + bn0 + tx * 4] = o;
    }
}

// ---------------- fused post_mp (256->128 via w12) + log_softmax ----------------
__global__ __launch_bounds__(128) void mp_lsm_kernel(
    const float* __restrict__ h,
    const float* __restrict__ w12, const float* __restrict__ b12,
    float* __restrict__ out)
{
    __shared__ float sh[256];
    __shared__ float red[128];
    int node = blockIdx.x;
    int t = threadIdx.x;
    sh[t]       = h[node * D + t];
    sh[t + 128] = h[node * D + t + 128];
    __syncthreads();

    float acc = b12[t];
#pragma unroll 8
    for (int k = 0; k < 256; k++)
        acc += sh[k] * w12[k * DOUT + t];

    red[t] = acc;
    __syncthreads();
    for (int s = 64; s > 0; s >>= 1) {
        if (t < s) red[t] = fmaxf(red[t], red[t + s]);
        __syncthreads();
    }
    float mx = red[0];
    __syncthreads();
    red[t] = expf(acc - mx);
    __syncthreads();
    for (int s = 64; s > 0; s >>= 1) {
        if (t < s) red[t] += red[t + s];
        __syncthreads();
    }
    float lse = mx + logf(red[0]);
    out[node * DOUT + t] = acc - lse;
}

// ---------------- launch ----------------
extern "C" void kernel_launch(void* const* d_in, const int* in_sizes, int n_in,
                              void* d_out, int out_size)
{
    const float* x  = (const float*)d_in[0];
    const void*  ei = d_in[1];
    const float* wl = (const float*)d_in[2];
    const float* bl = (const float*)d_in[3];
    const float* wr = (const float*)d_in[4];
    const float* w1 = (const float*)d_in[5];
    const float* b1 = (const float*)d_in[6];
    const float* w2 = (const float*)d_in[7];
    const float* b2 = (const float*)d_in[8];
    float* out = (float*)d_out;

    float *h, *h2, *agg, *w12, *b12;
    int *deg, *off, *cur, *srcp, *esrc, *edst, *flag;
    cudaGetSymbolAddress((void**)&h,    g_h);
    cudaGetSymbolAddress((void**)&h2,   g_h2);
    cudaGetSymbolAddress((void**)&agg,  g_agg);
    cudaGetSymbolAddress((void**)&w12,  g_w12);
    cudaGetSymbolAddress((void**)&b12,  g_b12);
    cudaGetSymbolAddress((void**)&deg,  g_deg);
    cudaGetSymbolAddress((void**)&off,  g_off);
    cudaGetSymbolAddress((void**)&cur,  g_cur);
    cudaGetSymbolAddress((void**)&srcp, g_src);
    cudaGetSymbolAddress((void**)&esrc, g_esrc);
    cudaGetSymbolAddress((void**)&edst, g_edst);
    cudaGetSymbolAddress((void**)&flag, g_flag);

    // Edge dtype probe + normalization, CSR build, post_mp weight folding
    probe_kernel        <<<1, 32>>>(ei, flag);
    convert_edges_kernel<<<(NE + 255) / 256, 256>>>(ei, flag, esrc, edst);
    zero_deg_kernel     <<<(NN + 255) / 256, 256>>>(deg);
    deg_count_kernel    <<<(NE + 255) / 256, 256>>>(edst, deg);
    scan_kernel         <<<1, 1024>>>(deg, off, cur);
    csr_fill_kernel     <<<(NE + 255) / 256, 256>>>(esrc, edst, cur, srcp);
    w12_kernel          <<<D, 128>>>(w1, b1, w2, b2, w12, b12);

    dim3 gg((NN + 127) / 128, D / 64);   // (391, 4)

    // layer 0: in = x
    agg_kernel   <<<NN, 256>>>(x, off, srcp, agg);
    gemm128_kernel<<<gg, 256>>>(agg, wl + 0 * D * D, bl + 0 * D, x,  wr + 0 * D * D, h,  NN);
    // layer 1: in = h
    agg_kernel   <<<NN, 256>>>(h, off, srcp, agg);
    gemm128_kernel<<<gg, 256>>>(agg, wl + 1 * D * D, bl + 1 * D, h,  wr + 1 * D * D, h2, NN);
    // layer 2: in = h2
    agg_kernel   <<<NN, 256>>>(h2, off, srcp, agg);
    gemm128_kernel<<<gg, 256>>>(agg, wl + 2 * D * D, bl + 2 * D, h2, wr + 2 * D * D, h,  NN);

    // fused post_mp (mp1 folded into w12) + log_softmax
    mp_lsm_kernel<<<NN, 128>>>(h, w12, b12, out);
}